// round 4
// baseline (speedup 1.0000x reference)
#include <cuda_runtime.h>
#include <cstdint>

// Problem constants
#define NN   8192     // total points
#define NBV  1024     // points per batch
#define BV   8        // batches
#define KV   9        // kernel taps
#define CV   32       // channels
#define CMV  128      // hidden
#define CWROW 288     // K*C floats per point

// ---------------- static scratch (no allocs allowed) ----------------
__device__ __align__(16) float g_cw[NN * CWROW];        // conv_w, [n][k][c]
__device__ __align__(16) float g_part[2 * NN * CV];     // sampled partials (nb halves)
__device__ __align__(16) float g_xl[NN * CV];           // leaky(sampled)
__device__ __align__(16) float g_x[NN * CV];            // bn1(xl)+weights
__device__ __align__(16) float g_hl[NN * CMV];          // leaky(x@W1+b1)
__device__ float g_s1[CV],  g_s1q[CV];                  // bn1 sums
__device__ float g_s2[CMV], g_s2q[CMV];                 // bn2 sums

// ---------------- K1: conv_w[n][k][c] = sum_d weights[n][d] * KW[k][d][c] ----------------
// grid = 192 blocks (64 n-blocks x 3 k-groups), 128 threads; each thread owns one n row.
__global__ __launch_bounds__(128) void k1_cw(const float* __restrict__ weights,
                                             const float* __restrict__ KW) {
    __shared__ __align__(16) float KWs[3 * CV * CV];   // 12KB: this block's 3 kernels
    __shared__ float tile[128 * 33];                   // transpose bounce, pad 33
    int t    = threadIdx.x;
    int nblk = blockIdx.x / 3;
    int kg   = blockIdx.x % 3;

    for (int i = t; i < 3 * CV * CV; i += 128) KWs[i] = KW[kg * 3 * CV * CV + i];
    __syncthreads();

    int n = nblk * 128 + t;
    float w[CV];
    const float4* wr = reinterpret_cast<const float4*>(&weights[(size_t)n * CV]);
#pragma unroll
    for (int q = 0; q < 8; q++) {
        float4 v = wr[q];
        w[q*4+0]=v.x; w[q*4+1]=v.y; w[q*4+2]=v.z; w[q*4+3]=v.w;
    }

    for (int kk = 0; kk < 3; kk++) {
        float acc[CV];
#pragma unroll
        for (int d = 0; d < CV; d++) acc[d] = 0.f;
#pragma unroll
        for (int c = 0; c < CV; c++) {
            float wc = w[c];
            const float4* kp = reinterpret_cast<const float4*>(&KWs[(kk * CV + c) * CV]);
#pragma unroll
            for (int q = 0; q < 8; q++) {
                float4 v = kp[q];
                acc[q*4+0] += wc * v.x;  acc[q*4+1] += wc * v.y;
                acc[q*4+2] += wc * v.z;  acc[q*4+3] += wc * v.w;
            }
        }
        __syncthreads();   // previous iter's tile readers are done
#pragma unroll
        for (int d = 0; d < CV; d++) tile[t * 33 + d] = acc[d];
        __syncthreads();
        int k = kg * 3 + kk;
        for (int idx = t; idx < 128 * CV; idx += 128) {   // coalesced store
            int nl = idx >> 5, c = idx & 31;
            g_cw[(size_t)(nblk * 128 + nl) * CWROW + k * CV + c] = tile[nl * 33 + c];
        }
    }
}

// ---------------- K2: the heavy fused Kmat*conv_w ----------------
// grid = 8 batches x 8 n-tiles(128) x 2 nb-halves(512) = 128 CTAs, 128 threads.
// Each thread owns one n row and 32 fp32 accumulators.
#define NBT 16
__global__ __launch_bounds__(128) void k2_sample(const float* __restrict__ pos,
                                                 const float* __restrict__ kpos) {
    __shared__ __align__(16) float cwS[NBT * CWROW];   // 18KB
    __shared__ float pS[NBT * 2];

    int t     = threadIdx.x;
    int bid   = blockIdx.x;
    int half  = bid & 1;
    int tileI = (bid >> 1) & 7;
    int b     = bid >> 4;

    int n = b * NBV + tileI * 128 + t;
    float px = pos[2 * n], py = pos[2 * n + 1];

    float gx[KV], gy[KV];
#pragma unroll
    for (int k = 0; k < KV; k++) { gx[k] = kpos[2 * k]; gy[k] = kpos[2 * k + 1]; }

    float acc[CV];
#pragma unroll
    for (int c = 0; c < CV; c++) acc[c] = 0.f;

    int nb0 = b * NBV + half * 512;
    for (int ch = 0; ch < 512; ch += NBT) {
        __syncthreads();
        // stage conv_w rows + neighbor positions for this chunk
        const float4* src = reinterpret_cast<const float4*>(&g_cw[(size_t)(nb0 + ch) * CWROW]);
        float4* dst = reinterpret_cast<float4*>(cwS);
        for (int i = t; i < NBT * (CWROW / 4); i += 128) dst[i] = src[i];
        for (int i = t; i < NBT * 2; i += 128) pS[i] = pos[(size_t)(nb0 + ch) * 2 + i];
        __syncthreads();

#pragma unroll 1
        for (int j = 0; j < NBT; j++) {
            float dX = px - pS[2 * j], dY = py - pS[2 * j + 1];
            float w[KV];
#pragma unroll
            for (int k = 0; k < KV; k++) {
                float ddx = dX - gx[k], ddy = dY - gy[k];
                float d2 = ddx * ddx + ddy * ddy;
                w[k] = __expf(-2.0f * d2);
            }
            const float4* cw4 = reinterpret_cast<const float4*>(&cwS[j * CWROW]);
#pragma unroll
            for (int k = 0; k < KV; k++) {
                float wk = w[k];
#pragma unroll
                for (int q = 0; q < 8; q++) {
                    float4 v = cw4[k * 8 + q];
                    acc[q*4+0] += wk * v.x;  acc[q*4+1] += wk * v.y;
                    acc[q*4+2] += wk * v.z;  acc[q*4+3] += wk * v.w;
                }
            }
        }
    }

    float* outp = &g_part[(size_t)half * NN * CV + (size_t)n * CV];
#pragma unroll
    for (int c = 0; c < CV; c++) outp[c] = acc[c];
}

// ---------------- K3: xl = leaky(part0+part1); per-channel sums (one block per channel) ----------------
__global__ void k3_xl(void) {
    int c = blockIdx.x, t = threadIdx.x;
    float s = 0.f, s2 = 0.f;
    for (int nn = t; nn < NN; nn += 256) {
        float v = g_part[(size_t)nn * CV + c] + g_part[(size_t)NN * CV + (size_t)nn * CV + c];
        float xl = (v >= 0.f) ? v : 0.01f * v;
        g_xl[(size_t)nn * CV + c] = xl;
        s += xl; s2 += xl * xl;
    }
    __shared__ float rs[256], rq[256];
    rs[t] = s; rq[t] = s2; __syncthreads();
    for (int o = 128; o > 0; o >>= 1) {
        if (t < o) { rs[t] += rs[t + o]; rq[t] += rq[t + o]; }
        __syncthreads();
    }
    if (t == 0) { g_s1[c] = rs[0]; g_s1q[c] = rq[0]; }
}

// ---------------- K4: x = bn1(xl)+weights; hl = leaky(x@W1+b1) ----------------
__global__ __launch_bounds__(128) void k4_mlp1(const float* __restrict__ weights,
                                               const float* __restrict__ gamma1,
                                               const float* __restrict__ beta1,
                                               const float* __restrict__ W1,
                                               const float* __restrict__ b1) {
    __shared__ __align__(16) float W1s[CV * CMV];   // 16KB
    __shared__ float sc1[CV], sh1[CV], b1s[CMV];
    int t = threadIdx.x;
    for (int i = t; i < CV * CMV; i += 128) W1s[i] = W1[i];
    if (t < CMV) b1s[t] = b1[t];
    if (t < CV) {
        float mu  = g_s1[t] * (1.0f / NN);
        float var = g_s1q[t] * (1.0f / NN) - mu * mu;
        float inv = rsqrtf(var + 1e-5f);
        float sc  = gamma1[t] * inv;
        sc1[t] = sc; sh1[t] = beta1[t] - mu * sc;
    }
    __syncthreads();

    int n = blockIdx.x * 128 + t;
    float x[CV];
#pragma unroll
    for (int c = 0; c < CV; c++) {
        float xl = g_xl[(size_t)n * CV + c];
        float xv = fmaf(xl, sc1[c], sh1[c]) + weights[(size_t)n * CV + c];
        x[c] = xv;
        g_x[(size_t)n * CV + c] = xv;
    }
#pragma unroll 1
    for (int jb = 0; jb < CMV; jb += 32) {
        float acc[32];
#pragma unroll
        for (int j = 0; j < 32; j++) acc[j] = b1s[jb + j];
#pragma unroll
        for (int c = 0; c < CV; c++) {
            float xc = x[c];
            const float4* wr = reinterpret_cast<const float4*>(&W1s[c * CMV + jb]);
#pragma unroll
            for (int q = 0; q < 8; q++) {
                float4 v = wr[q];
                acc[q*4+0] += xc * v.x;  acc[q*4+1] += xc * v.y;
                acc[q*4+2] += xc * v.z;  acc[q*4+3] += xc * v.w;
            }
        }
#pragma unroll
        for (int j = 0; j < 32; j++) {
            float h = acc[j];
            g_hl[(size_t)n * CMV + jb + j] = (h >= 0.f) ? h : 0.01f * h;
        }
    }
}

// ---------------- K5: bn2 per-channel sums over hl (one block per channel) ----------------
__global__ void k5_stats2(void) {
    int c = blockIdx.x, t = threadIdx.x;
    float s = 0.f, s2 = 0.f;
    for (int nn = t; nn < NN; nn += 256) {
        float v = g_hl[(size_t)nn * CMV + c];
        s += v; s2 += v * v;
    }
    __shared__ float rs[256], rq[256];
    rs[t] = s; rq[t] = s2; __syncthreads();
    for (int o = 128; o > 0; o >>= 1) {
        if (t < o) { rs[t] += rs[t + o]; rq[t] += rq[t + o]; }
        __syncthreads();
    }
    if (t == 0) { g_s2[c] = rs[0]; g_s2q[c] = rq[0]; }
}

// ---------------- K6: h = bn2(hl); mlp_out = h@W2 + b2; write outputs ----------------
__global__ __launch_bounds__(128) void k6_final(const float* __restrict__ pos,
                                                const float* __restrict__ gamma2,
                                                const float* __restrict__ beta2,
                                                const float* __restrict__ W2,
                                                const float* __restrict__ b2,
                                                float* __restrict__ out) {
    __shared__ float W2s[CMV * 34];   // 17.4KB
    __shared__ float sc2[CMV], sh2[CMV], b2s[34];
    int t = threadIdx.x;
    for (int i = t; i < CMV * 34; i += 128) W2s[i] = W2[i];
    if (t < 34) b2s[t] = b2[t];
    if (t < CMV) {
        float mu  = g_s2[t] * (1.0f / NN);
        float var = g_s2q[t] * (1.0f / NN) - mu * mu;
        float inv = rsqrtf(var + 1e-5f);
        float sc  = gamma2[t] * inv;
        sc2[t] = sc; sh2[t] = beta2[t] - mu * sc;
    }
    __syncthreads();

    int n = blockIdx.x * 128 + t;
    float acc[34];
#pragma unroll
    for (int j = 0; j < 34; j++) acc[j] = b2s[j];
#pragma unroll 1
    for (int d = 0; d < CMV; d++) {
        float hv = g_hl[(size_t)n * CMV + d];
        float hn = fmaf(hv, sc2[d], sh2[d]);
        const float* wr = &W2s[d * 34];
#pragma unroll
        for (int j = 0; j < 34; j++) acc[j] += hn * wr[j];
    }

    out[2 * n + 0] = pos[2 * n + 0] + acc[0];
    out[2 * n + 1] = pos[2 * n + 1] + acc[1];
    float* ow = &out[(size_t)NN * 2 + (size_t)n * CV];
#pragma unroll
    for (int c = 0; c < CV; c++) ow[c] = g_x[(size_t)n * CV + c] + acc[2 + c];
}

// ---------------- launch ----------------
extern "C" void kernel_launch(void* const* d_in, const int* in_sizes, int n_in,
                              void* d_out, int out_size) {
    (void)in_sizes; (void)n_in; (void)out_size;
    const float* positions = (const float*)d_in[0];
    const float* weights   = (const float*)d_in[1];
    // d_in[2] = batch (int32, uniform NB) — unused
    const float* kpos      = (const float*)d_in[3];
    const float* KW        = (const float*)d_in[4];
    const float* g1        = (const float*)d_in[5];
    const float* be1       = (const float*)d_in[6];
    const float* W1        = (const float*)d_in[7];
    const float* b1        = (const float*)d_in[8];
    const float* g2        = (const float*)d_in[9];
    const float* be2       = (const float*)d_in[10];
    const float* W2        = (const float*)d_in[11];
    const float* b2        = (const float*)d_in[12];
    float* out = (float*)d_out;

    k1_cw<<<192, 128>>>(weights, KW);
    k2_sample<<<128, 128>>>(positions, kpos);
    k3_xl<<<CV, 256>>>();
    k4_mlp1<<<NN / 128, 128>>>(weights, g1, be1, W1, b1);
    k5_stats2<<<CMV, 256>>>();
    k6_final<<<NN / 128, 128>>>(positions, g2, be2, W2, b2, out);
}

// round 5
// speedup vs baseline: 1.4739x; 1.4739x over previous
#include <cuda_runtime.h>
#include <cstdint>

// Problem constants
#define NN   8192     // total points
#define NBV  1024     // points per batch
#define BV   8        // batches
#define KV   9        // kernel taps
#define CV   32       // channels
#define CMV  128      // hidden
#define CWROW 288     // K*C floats per point

// ---------------- static scratch (no allocs allowed) ----------------
__device__ __align__(16) float g_cw[NN * CWROW];        // conv_w, [n][k][c]
__device__ __align__(16) float g_part[4 * NN * CV];     // sampled partials (4 nb quarters)
__device__ __align__(16) float g_xl[NN * CV];           // leaky(sampled)
__device__ __align__(16) float g_x[NN * CV];            // bn1(xl)+weights
__device__ __align__(16) float g_hl[NN * CMV];          // leaky(x@W1+b1)
__device__ float g_p1s[64 * CV],  g_p1q[64 * CV];       // bn1 per-block partials
__device__ float g_p2s[64 * CMV], g_p2q[64 * CMV];      // bn2 per-block partials

// ---------------- packed f32x2 helpers ----------------
__device__ __forceinline__ unsigned long long pack2(float a, float b) {
    unsigned long long r;
    asm("mov.b64 %0, {%1, %2};" : "=l"(r) : "f"(a), "f"(b));
    return r;
}
__device__ __forceinline__ void unpack2(unsigned long long v, float& a, float& b) {
    asm("mov.b64 {%0, %1}, %2;" : "=f"(a), "=f"(b) : "l"(v));
}
__device__ __forceinline__ void fma2(unsigned long long& d, unsigned long long a,
                                     unsigned long long b) {
    asm("fma.rn.f32x2 %0, %1, %2, %3;" : "=l"(d) : "l"(a), "l"(b), "l"(d));
}

// ---------------- K1: conv_w[n][k][c] = sum_d weights[n][d] * KW[k][d][c] ----------------
__global__ __launch_bounds__(128) void k1_cw(const float* __restrict__ weights,
                                             const float* __restrict__ KW) {
    __shared__ __align__(16) float KWs[3 * CV * CV];
    __shared__ float tile[128 * 33];
    int t    = threadIdx.x;
    int nblk = blockIdx.x / 3;
    int kg   = blockIdx.x % 3;

    for (int i = t; i < 3 * CV * CV; i += 128) KWs[i] = KW[kg * 3 * CV * CV + i];
    __syncthreads();

    int n = nblk * 128 + t;
    float w[CV];
    const float4* wr = reinterpret_cast<const float4*>(&weights[(size_t)n * CV]);
#pragma unroll
    for (int q = 0; q < 8; q++) {
        float4 v = wr[q];
        w[q*4+0]=v.x; w[q*4+1]=v.y; w[q*4+2]=v.z; w[q*4+3]=v.w;
    }

    for (int kk = 0; kk < 3; kk++) {
        float acc[CV];
#pragma unroll
        for (int d = 0; d < CV; d++) acc[d] = 0.f;
#pragma unroll
        for (int c = 0; c < CV; c++) {
            float wc = w[c];
            const float4* kp = reinterpret_cast<const float4*>(&KWs[(kk * CV + c) * CV]);
#pragma unroll
            for (int q = 0; q < 8; q++) {
                float4 v = kp[q];
                acc[q*4+0] += wc * v.x;  acc[q*4+1] += wc * v.y;
                acc[q*4+2] += wc * v.z;  acc[q*4+3] += wc * v.w;
            }
        }
        __syncthreads();
#pragma unroll
        for (int d = 0; d < CV; d++) tile[t * 33 + d] = acc[d];
        __syncthreads();
        int k = kg * 3 + kk;
        for (int idx = t; idx < 128 * CV; idx += 128) {
            int nl = idx >> 5, c = idx & 31;
            g_cw[(size_t)(nblk * 128 + nl) * CWROW + k * CV + c] = tile[nl * 33 + c];
        }
    }
}

// ---------------- K2: fused Kmat * conv_w with packed f32x2 FMA ----------------
// grid = 8 batches x 4 n-tiles(256) x 4 nb-quarters(256) = 128 CTAs, 256 threads.
#define NBT 16
__global__ __launch_bounds__(256) void k2_sample(const float* __restrict__ pos,
                                                 const float* __restrict__ kpos) {
    __shared__ __align__(16) float cwS[NBT * CWROW];   // 18KB
    __shared__ float pS[NBT * 2];

    int t    = threadIdx.x;
    int bid  = blockIdx.x;
    int q    = bid & 3;          // nb quarter
    int tile = (bid >> 2) & 3;   // n tile
    int b    = bid >> 4;         // batch

    int n = b * NBV + tile * 256 + t;
    float px = pos[2 * n], py = pos[2 * n + 1];

    float gx[KV], gy[KV];
#pragma unroll
    for (int k = 0; k < KV; k++) { gx[k] = kpos[2 * k]; gy[k] = kpos[2 * k + 1]; }

    unsigned long long acc2[16];
#pragma unroll
    for (int i = 0; i < 16; i++) acc2[i] = 0ULL;

    int nb0 = b * NBV + q * 256;
    for (int ch = 0; ch < 256; ch += NBT) {
        __syncthreads();
        const float4* src = reinterpret_cast<const float4*>(&g_cw[(size_t)(nb0 + ch) * CWROW]);
        float4* dst = reinterpret_cast<float4*>(cwS);
        for (int i = t; i < NBT * (CWROW / 4); i += 256) dst[i] = src[i];
        for (int i = t; i < NBT * 2; i += 256) pS[i] = pos[(size_t)(nb0 + ch) * 2 + i];
        __syncthreads();

#pragma unroll 1
        for (int j = 0; j < NBT; j++) {
            float dX = px - pS[2 * j], dY = py - pS[2 * j + 1];
            float w[KV];
#pragma unroll
            for (int k = 0; k < KV; k++) {
                float ddx = dX - gx[k], ddy = dY - gy[k];
                w[k] = __expf(-2.0f * (ddx * ddx + ddy * ddy));
            }
#pragma unroll
            for (int k = 0; k < KV; k++) {
                unsigned long long w2 = pack2(w[k], w[k]);
                const ulonglong2* cw2 =
                    reinterpret_cast<const ulonglong2*>(&cwS[j * CWROW + k * CV]);
#pragma unroll
                for (int p = 0; p < 8; p++) {
                    ulonglong2 v = cw2[p];
                    fma2(acc2[2 * p],     v.x, w2);
                    fma2(acc2[2 * p + 1], v.y, w2);
                }
            }
        }
    }

    float* outp = &g_part[(size_t)q * NN * CV + (size_t)n * CV];
#pragma unroll
    for (int p = 0; p < 16; p++) {
        float a, bb;
        unpack2(acc2[p], a, bb);
        outp[2 * p] = a; outp[2 * p + 1] = bb;
    }
}

// ---------------- K3: xl = leaky(sum of 4 partials); coalesced per-block stats ----------------
// grid = 64 blocks x 256 threads; block handles 128 rows. Thread channel = t&31 (const).
__global__ __launch_bounds__(256) void k3_xl(void) {
    int t = threadIdx.x, blk = blockIdx.x;
    size_t base = (size_t)blk * 128 * CV;
    float s = 0.f, s2 = 0.f;
    for (int idx = t; idx < 128 * CV; idx += 256) {
        size_t off = base + idx;
        float v = g_part[off] + g_part[(size_t)NN * CV + off]
                + g_part[2 * (size_t)NN * CV + off] + g_part[3 * (size_t)NN * CV + off];
        float xl = (v >= 0.f) ? v : 0.01f * v;
        g_xl[off] = xl;
        s += xl; s2 += xl * xl;
    }
    __shared__ float rs[256], rq[256];
    rs[t] = s; rq[t] = s2; __syncthreads();
    if (t < CV) {
        float a = 0.f, bb = 0.f;
#pragma unroll
        for (int j = 0; j < 256; j += 32) { a += rs[t + j]; bb += rq[t + j]; }
        g_p1s[blk * CV + t] = a; g_p1q[blk * CV + t] = bb;
    }
}

// ---------------- K4: x = bn1(xl)+weights; hl = leaky(x@W1+b1) ----------------
// grid = 128 blocks x 256 threads; block = 64 n-rows x 4 j-quarters(32 each).
__global__ __launch_bounds__(256) void k4_mlp1(const float* __restrict__ weights,
                                               const float* __restrict__ gamma1,
                                               const float* __restrict__ beta1,
                                               const float* __restrict__ W1,
                                               const float* __restrict__ b1) {
    __shared__ __align__(16) float W1s[CV * CMV];   // 16KB
    __shared__ float xS[64 * 33];                   // padded x tile
    __shared__ float sc1[CV], sh1[CV], b1s[CMV];
    int t = threadIdx.x, blk = blockIdx.x;
    int n0 = blk * 64;

    for (int i = t; i < CV * CMV; i += 256) W1s[i] = W1[i];
    if (t < CMV) b1s[t] = b1[t];
    for (int i = t; i < 64 * CV; i += 256) {
        int nl = i >> 5, c = i & 31;
        xS[nl * 33 + c] = g_xl[(size_t)(n0 + nl) * CV + c];
    }
    if (t < CV) {
        float s = 0.f, s2 = 0.f;
#pragma unroll 8
        for (int j = 0; j < 64; j++) { s += g_p1s[j * CV + t]; s2 += g_p1q[j * CV + t]; }
        float mu  = s * (1.0f / NN);
        float var = s2 * (1.0f / NN) - mu * mu;
        float inv = rsqrtf(var + 1e-5f);
        float sc  = gamma1[t] * inv;
        sc1[t] = sc; sh1[t] = beta1[t] - mu * sc;
    }
    __syncthreads();

    // x = bn1(xl) + weights, in place in xS; also store g_x (coalesced)
    for (int i = t; i < 64 * CV; i += 256) {
        int nl = i >> 5, c = i & 31;
        float xv = fmaf(xS[nl * 33 + c], sc1[c], sh1[c])
                 + weights[(size_t)(n0 + nl) * CV + c];
        xS[nl * 33 + c] = xv;
        g_x[(size_t)(n0 + nl) * CV + c] = xv;
    }
    __syncthreads();

    int nl = t & 63, jq = t >> 6, jb = jq * 32;
    float acc[32];
#pragma unroll
    for (int j = 0; j < 32; j++) acc[j] = b1s[jb + j];
#pragma unroll
    for (int c = 0; c < CV; c++) {
        float xc = xS[nl * 33 + c];
        const float4* wr = reinterpret_cast<const float4*>(&W1s[c * CMV + jb]);
#pragma unroll
        for (int p = 0; p < 8; p++) {
            float4 v = wr[p];
            acc[p*4+0] += xc * v.x;  acc[p*4+1] += xc * v.y;
            acc[p*4+2] += xc * v.z;  acc[p*4+3] += xc * v.w;
        }
    }
    float* hl = &g_hl[(size_t)(n0 + nl) * CMV + jb];
#pragma unroll
    for (int p = 0; p < 8; p++) {
        float4 v;
        float h0 = acc[p*4+0], h1 = acc[p*4+1], h2 = acc[p*4+2], h3 = acc[p*4+3];
        v.x = (h0 >= 0.f) ? h0 : 0.01f * h0;
        v.y = (h1 >= 0.f) ? h1 : 0.01f * h1;
        v.z = (h2 >= 0.f) ? h2 : 0.01f * h2;
        v.w = (h3 >= 0.f) ? h3 : 0.01f * h3;
        reinterpret_cast<float4*>(hl)[p] = v;
    }
}

// ---------------- K5: bn2 partial sums, coalesced ----------------
// grid = 64 blocks x 256 threads; block handles 128 rows. Thread channel = t&127.
__global__ __launch_bounds__(256) void k5_stats2(void) {
    int t = threadIdx.x, blk = blockIdx.x;
    size_t base = (size_t)blk * 128 * CMV;
    float s = 0.f, s2 = 0.f;
    for (int idx = t; idx < 128 * CMV; idx += 256) {
        float v = g_hl[base + idx];
        s += v; s2 += v * v;
    }
    __shared__ float rs[256], rq[256];
    rs[t] = s; rq[t] = s2; __syncthreads();
    if (t < CMV) {
        g_p2s[blk * CMV + t] = rs[t] + rs[t + CMV];
        g_p2q[blk * CMV + t] = rq[t] + rq[t + CMV];
    }
}

// ---------------- K6: h = bn2(hl); mlp_out = h@W2 + b2; write outputs ----------------
// grid = 128 blocks x 256 threads; block = 64 n-rows x 4 j-groups(9 each, padded to 36).
__global__ __launch_bounds__(256) void k6_final(const float* __restrict__ pos,
                                                const float* __restrict__ gamma2,
                                                const float* __restrict__ beta2,
                                                const float* __restrict__ W2,
                                                const float* __restrict__ b2,
                                                float* __restrict__ out) {
    __shared__ float W2s[CMV * 36];   // 18KB, padded 34->36
    __shared__ float sc2[CMV], sh2[CMV], b2s[36];
    __shared__ float rs[256], rq[256];
    int t = threadIdx.x, blk = blockIdx.x;
    int n0 = blk * 64;

    for (int i = t; i < CMV * 36; i += 256) {
        int d = i / 36, j = i % 36;
        W2s[i] = (j < 34) ? W2[d * 34 + j] : 0.f;
    }
    if (t < 36) b2s[t] = (t < 34) ? b2[t] : 0.f;
    {
        int c = t & 127, hf = t >> 7;
        float s = 0.f, s2 = 0.f;
#pragma unroll 8
        for (int j = hf * 32; j < hf * 32 + 32; j++) {
            s += g_p2s[j * CMV + c]; s2 += g_p2q[j * CMV + c];
        }
        rs[t] = s; rq[t] = s2;
    }
    __syncthreads();
    if (t < CMV) {
        float s  = rs[t] + rs[t + 128];
        float s2 = rq[t] + rq[t + 128];
        float mu  = s * (1.0f / NN);
        float var = s2 * (1.0f / NN) - mu * mu;
        float inv = rsqrtf(var + 1e-5f);
        float sc  = gamma2[t] * inv;
        sc2[t] = sc; sh2[t] = beta2[t] - mu * sc;
    }
    __syncthreads();

    int nl = t & 63, qq = t >> 6, jb = qq * 9;
    int n = n0 + nl;
    float acc[9];
#pragma unroll
    for (int j = 0; j < 9; j++) acc[j] = b2s[jb + j];
#pragma unroll 4
    for (int d = 0; d < CMV; d++) {
        float hv = g_hl[(size_t)n * CMV + d];
        float hn = fmaf(hv, sc2[d], sh2[d]);
        const float* wr = &W2s[d * 36 + jb];
#pragma unroll
        for (int j = 0; j < 9; j++) acc[j] += hn * wr[j];
    }

#pragma unroll
    for (int j = 0; j < 9; j++) {
        int jg = jb + j;
        if (jg == 0)      out[2 * n + 0] = pos[2 * n + 0] + acc[j];
        else if (jg == 1) out[2 * n + 1] = pos[2 * n + 1] + acc[j];
        else if (jg < 34)
            out[(size_t)NN * 2 + (size_t)n * CV + (jg - 2)]
                = g_x[(size_t)n * CV + (jg - 2)] + acc[j];
    }
}

// ---------------- launch ----------------
extern "C" void kernel_launch(void* const* d_in, const int* in_sizes, int n_in,
                              void* d_out, int out_size) {
    (void)in_sizes; (void)n_in; (void)out_size;
    const float* positions = (const float*)d_in[0];
    const float* weights   = (const float*)d_in[1];
    // d_in[2] = batch (int32, uniform NB) — unused
    const float* kpos      = (const float*)d_in[3];
    const float* KW        = (const float*)d_in[4];
    const float* g1        = (const float*)d_in[5];
    const float* be1       = (const float*)d_in[6];
    const float* W1        = (const float*)d_in[7];
    const float* b1        = (const float*)d_in[8];
    const float* g2        = (const float*)d_in[9];
    const float* be2       = (const float*)d_in[10];
    const float* W2        = (const float*)d_in[11];
    const float* b2        = (const float*)d_in[12];
    float* out = (float*)d_out;

    k1_cw<<<192, 128>>>(weights, KW);
    k2_sample<<<128, 256>>>(positions, kpos);
    k3_xl<<<64, 256>>>();
    k4_mlp1<<<128, 256>>>(weights, g1, be1, W1, b1);
    k5_stats2<<<64, 256>>>();
    k6_final<<<128, 256>>>(positions, g2, be2, W2, b2, out);
}

// round 6
// speedup vs baseline: 1.7137x; 1.1627x over previous
#include <cuda_runtime.h>
#include <cstdint>

// Problem constants
#define NN   8192     // total points
#define NBV  1024     // points per batch
#define BV   8        // batches
#define KV   9        // kernel taps
#define CV   32       // channels
#define CMV  128      // hidden
#define CWROW 288     // K*C floats per point

// ---------------- static scratch (no allocs allowed) ----------------
__device__ __align__(16) float g_cw[NN * CWROW];        // conv_w, [n][k][c]
__device__ __align__(16) float g_part[8 * NN * CV];     // sampled partials (8 nb eighths)
__device__ __align__(16) float g_xl[NN * CV];           // leaky(sampled)
__device__ __align__(16) float g_x[NN * CV];            // bn1(xl)+weights
__device__ __align__(16) float g_hl[NN * CMV];          // leaky(x@W1+b1)
__device__ float g_p1s[64 * CV],  g_p1q[64 * CV];       // bn1 per-block partials
__device__ float g_p2s[64 * CMV], g_p2q[64 * CMV];      // bn2 per-block partials

// ---------------- packed f32x2 helpers ----------------
__device__ __forceinline__ unsigned long long pack2(float a, float b) {
    unsigned long long r;
    asm("mov.b64 %0, {%1, %2};" : "=l"(r) : "f"(a), "f"(b));
    return r;
}
__device__ __forceinline__ void unpack2(unsigned long long v, float& a, float& b) {
    asm("mov.b64 {%0, %1}, %2;" : "=f"(a), "=f"(b) : "l"(v));
}
__device__ __forceinline__ void fma2(unsigned long long& d, unsigned long long a,
                                     unsigned long long b) {
    asm("fma.rn.f32x2 %0, %1, %2, %3;" : "=l"(d) : "l"(a), "l"(b), "l"(d));
}

// ---------------- K1: conv_w[n][k][d] = sum_c weights[n][c] * KW[k][c][d] ----------------
// 288 threads = (k = t/32, d = t%32); 128 blocks x 64 rows. KW cached in registers.
__global__ __launch_bounds__(288) void k1_cw(const float* __restrict__ weights,
                                             const float* __restrict__ KW) {
    __shared__ __align__(16) float wS[64 * CV];   // 8KB
    int t = threadIdx.x;
    int k = t / 32, d = t % 32;
    int n0 = blockIdx.x * 64;

    float KWr[CV];
#pragma unroll
    for (int c = 0; c < CV; c++) KWr[c] = KW[k * CV * CV + c * CV + d];  // coalesced per warp

    for (int i = t; i < 64 * CV; i += 288) wS[i] = weights[(size_t)n0 * CV + i];
    __syncthreads();

#pragma unroll 2
    for (int nl = 0; nl < 64; nl++) {
        const float4* wr = reinterpret_cast<const float4*>(&wS[nl * CV]);
        float acc = 0.f;
#pragma unroll
        for (int p = 0; p < 8; p++) {
            float4 v = wr[p];   // broadcast LDS.128
            acc += KWr[4*p+0] * v.x + KWr[4*p+1] * v.y
                 + KWr[4*p+2] * v.z + KWr[4*p+3] * v.w;
        }
        g_cw[(size_t)(n0 + nl) * CWROW + t] = acc;   // fully coalesced (288 consecutive)
    }
}

// ---------------- K2: fused Kmat * conv_w, packed f32x2 FMA, separable gaussians ----------------
// grid = 8 batches x 8 n-tiles(128) x 8 nb-eighths(128) = 512 CTAs, 128 threads.
#define NBT 16
__global__ __launch_bounds__(128) void k2_sample(const float* __restrict__ pos,
                                                 const float* __restrict__ kpos) {
    __shared__ __align__(16) float cwS[NBT * CWROW];   // 18KB
    __shared__ float pS[NBT * 2];

    int t    = threadIdx.x;
    int bid  = blockIdx.x;
    int q    = bid & 7;          // nb eighth
    int tile = (bid >> 3) & 7;   // n tile
    int b    = bid >> 6;         // batch

    int n = b * NBV + tile * 128 + t;
    float px = pos[2 * n], py = pos[2 * n + 1];

    // kernel grid is separable: kpos[k] = (g[k/3], g[k%3])
    float gvx[3], gvy[3];
#pragma unroll
    for (int i = 0; i < 3; i++) { gvx[i] = kpos[2 * (3 * i)]; gvy[i] = kpos[2 * i + 1]; }

    unsigned long long acc2[16];
#pragma unroll
    for (int i = 0; i < 16; i++) acc2[i] = 0ULL;

    int nb0 = b * NBV + q * 128;
    for (int ch = 0; ch < 128; ch += NBT) {
        __syncthreads();
        const float4* src = reinterpret_cast<const float4*>(&g_cw[(size_t)(nb0 + ch) * CWROW]);
        float4* dst = reinterpret_cast<float4*>(cwS);
        for (int i = t; i < NBT * (CWROW / 4); i += 128) dst[i] = src[i];
        for (int i = t; i < NBT * 2; i += 128) pS[i] = pos[(size_t)(nb0 + ch) * 2 + i];
        __syncthreads();

#pragma unroll 1
        for (int j = 0; j < NBT; j++) {
            float dX = px - pS[2 * j], dY = py - pS[2 * j + 1];
            float ex[3], ey[3];
#pragma unroll
            for (int g = 0; g < 3; g++) {
                float ax = dX - gvx[g];
                float ay = dY - gvy[g];
                ex[g] = __expf(-2.0f * ax * ax);
                ey[g] = __expf(-2.0f * ay * ay);
            }
#pragma unroll
            for (int k = 0; k < KV; k++) {
                float w = ex[k / 3] * ey[k % 3];
                unsigned long long w2 = pack2(w, w);
                const ulonglong2* cw2 =
                    reinterpret_cast<const ulonglong2*>(&cwS[j * CWROW + k * CV]);
#pragma unroll
                for (int p = 0; p < 8; p++) {
                    ulonglong2 v = cw2[p];
                    fma2(acc2[2 * p],     v.x, w2);
                    fma2(acc2[2 * p + 1], v.y, w2);
                }
            }
        }
    }

    float* outp = &g_part[(size_t)q * NN * CV + (size_t)n * CV];
#pragma unroll
    for (int p = 0; p < 8; p++) {
        float4 v;
        unpack2(acc2[2 * p],     v.x, v.y);
        unpack2(acc2[2 * p + 1], v.z, v.w);
        reinterpret_cast<float4*>(outp)[p] = v;
    }
}

// ---------------- K3: xl = leaky(sum of 8 partials); coalesced per-block stats ----------------
__global__ __launch_bounds__(256) void k3_xl(void) {
    int t = threadIdx.x, blk = blockIdx.x;
    size_t base = (size_t)blk * 128 * CV;
    float s = 0.f, s2 = 0.f;
    for (int idx = t; idx < 128 * CV; idx += 256) {
        size_t off = base + idx;
        float v = 0.f;
#pragma unroll
        for (int sl = 0; sl < 8; sl++) v += g_part[(size_t)sl * NN * CV + off];
        float xl = (v >= 0.f) ? v : 0.01f * v;
        g_xl[off] = xl;
        s += xl; s2 += xl * xl;
    }
    __shared__ float rs[256], rq[256];
    rs[t] = s; rq[t] = s2; __syncthreads();
    if (t < CV) {
        float a = 0.f, bb = 0.f;
#pragma unroll
        for (int j = 0; j < 256; j += 32) { a += rs[t + j]; bb += rq[t + j]; }
        g_p1s[blk * CV + t] = a; g_p1q[blk * CV + t] = bb;
    }
}

// ---------------- K4: x = bn1(xl)+weights; hl = leaky(x@W1+b1), FFMA2 ----------------
// grid = 128 blocks x 256 threads; block = 64 n-rows x 4 j-quarters(32 each).
__global__ __launch_bounds__(256) void k4_mlp1(const float* __restrict__ weights,
                                               const float* __restrict__ gamma1,
                                               const float* __restrict__ beta1,
                                               const float* __restrict__ W1,
                                               const float* __restrict__ b1) {
    __shared__ __align__(16) float W1s[CV * CMV];   // 16KB
    __shared__ float xS[64 * 33];
    __shared__ float sc1[CV], sh1[CV], b1s[CMV];
    int t = threadIdx.x, blk = blockIdx.x;
    int n0 = blk * 64;

    for (int i = t; i < CV * CMV; i += 256) W1s[i] = W1[i];
    if (t < CMV) b1s[t] = b1[t];
    for (int i = t; i < 64 * CV; i += 256) {
        int nl = i >> 5, c = i & 31;
        xS[nl * 33 + c] = g_xl[(size_t)(n0 + nl) * CV + c];
    }
    if (t < CV) {
        float s = 0.f, s2 = 0.f;
#pragma unroll 8
        for (int j = 0; j < 64; j++) { s += g_p1s[j * CV + t]; s2 += g_p1q[j * CV + t]; }
        float mu  = s * (1.0f / NN);
        float var = s2 * (1.0f / NN) - mu * mu;
        float inv = rsqrtf(var + 1e-5f);
        float sc  = gamma1[t] * inv;
        sc1[t] = sc; sh1[t] = beta1[t] - mu * sc;
    }
    __syncthreads();

    for (int i = t; i < 64 * CV; i += 256) {
        int nl = i >> 5, c = i & 31;
        float xv = fmaf(xS[nl * 33 + c], sc1[c], sh1[c])
                 + weights[(size_t)(n0 + nl) * CV + c];
        xS[nl * 33 + c] = xv;
        g_x[(size_t)(n0 + nl) * CV + c] = xv;
    }
    __syncthreads();

    int nl = t & 63, jq = t >> 6, jb = jq * 32;
    unsigned long long acc2[16];
#pragma unroll
    for (int i = 0; i < 16; i++) acc2[i] = pack2(b1s[jb + 2 * i], b1s[jb + 2 * i + 1]);
#pragma unroll
    for (int c = 0; c < CV; c++) {
        float xc = xS[nl * 33 + c];
        unsigned long long xc2 = pack2(xc, xc);
        const ulonglong2* wr = reinterpret_cast<const ulonglong2*>(&W1s[c * CMV + jb]);
#pragma unroll
        for (int p = 0; p < 8; p++) {
            ulonglong2 v = wr[p];   // broadcast LDS.128
            fma2(acc2[2 * p],     v.x, xc2);
            fma2(acc2[2 * p + 1], v.y, xc2);
        }
    }
    float* hl = &g_hl[(size_t)(n0 + nl) * CMV + jb];
#pragma unroll
    for (int p = 0; p < 8; p++) {
        float h0, h1, h2, h3;
        unpack2(acc2[2 * p],     h0, h1);
        unpack2(acc2[2 * p + 1], h2, h3);
        float4 v;
        v.x = (h0 >= 0.f) ? h0 : 0.01f * h0;
        v.y = (h1 >= 0.f) ? h1 : 0.01f * h1;
        v.z = (h2 >= 0.f) ? h2 : 0.01f * h2;
        v.w = (h3 >= 0.f) ? h3 : 0.01f * h3;
        reinterpret_cast<float4*>(hl)[p] = v;
    }
}

// ---------------- K5: bn2 partial sums, coalesced ----------------
__global__ __launch_bounds__(256) void k5_stats2(void) {
    int t = threadIdx.x, blk = blockIdx.x;
    size_t base = (size_t)blk * 128 * CMV;
    float s = 0.f, s2 = 0.f;
    for (int idx = t; idx < 128 * CMV; idx += 256) {
        float v = g_hl[base + idx];
        s += v; s2 += v * v;
    }
    __shared__ float rs[256], rq[256];
    rs[t] = s; rq[t] = s2; __syncthreads();
    if (t < CMV) {
        g_p2s[blk * CMV + t] = rs[t] + rs[t + CMV];
        g_p2q[blk * CMV + t] = rq[t] + rq[t + CMV];
    }
}

// ---------------- K6: h = bn2(hl); mlp_out = h@W2 + b2; outputs via SMEM bounce ----------------
// grid = 128 blocks x 256 threads; block = 64 n-rows x 4 j-groups(9 each).
__global__ __launch_bounds__(256) void k6_final(const float* __restrict__ pos,
                                                const float* __restrict__ gamma2,
                                                const float* __restrict__ beta2,
                                                const float* __restrict__ W2,
                                                const float* __restrict__ b2,
                                                float* __restrict__ out) {
    __shared__ float W2s[CMV * 36];     // 18KB (padded 34->36)
    __shared__ float hlS[64 * 129];     // 33KB normalized h tile, pad 129
    __shared__ float outS[64 * 36];     // 9.2KB output bounce
    __shared__ float sc2[CMV], sh2[CMV], b2s[36];
    __shared__ float rs[256], rq[256];
    int t = threadIdx.x, blk = blockIdx.x;
    int n0 = blk * 64;

    for (int i = t; i < CMV * 36; i += 256) {
        int d = i / 36, j = i % 36;
        W2s[i] = (j < 34) ? W2[d * 34 + j] : 0.f;
    }
    if (t < 36) b2s[t] = (t < 34) ? b2[t] : 0.f;
    {
        int c = t & 127, hf = t >> 7;
        float s = 0.f, s2 = 0.f;
#pragma unroll 8
        for (int j = hf * 32; j < hf * 32 + 32; j++) {
            s += g_p2s[j * CMV + c]; s2 += g_p2q[j * CMV + c];
        }
        rs[t] = s; rq[t] = s2;
    }
    __syncthreads();
    if (t < CMV) {
        float s  = rs[t] + rs[t + 128];
        float s2 = rq[t] + rq[t + 128];
        float mu  = s * (1.0f / NN);
        float var = s2 * (1.0f / NN) - mu * mu;
        float inv = rsqrtf(var + 1e-5f);
        float sc  = gamma2[t] * inv;
        sc2[t] = sc; sh2[t] = beta2[t] - mu * sc;
    }
    __syncthreads();

    // stage normalized h tile, coalesced reads
    for (int i = t; i < 64 * CMV; i += 256) {
        int nl = i >> 7, d = i & 127;
        hlS[nl * 129 + d] = fmaf(g_hl[(size_t)n0 * CMV + i], sc2[d], sh2[d]);
    }
    __syncthreads();

    int nl = t & 63, qq = t >> 6, jb = qq * 9;
    float acc[9];
#pragma unroll
    for (int j = 0; j < 9; j++) acc[j] = b2s[jb + j];
#pragma unroll 4
    for (int d = 0; d < CMV; d++) {
        float hn = hlS[nl * 129 + d];
        const float* wr = &W2s[d * 36 + jb];
#pragma unroll
        for (int j = 0; j < 9; j++) acc[j] += hn * wr[j];
    }
#pragma unroll
    for (int j = 0; j < 9; j++) outS[nl * 36 + jb + j] = acc[j];
    __syncthreads();

    // coalesced output writes
    for (int i = t; i < 64 * 34; i += 256) {
        int nl2 = i / 34, jg = i % 34;
        int n = n0 + nl2;
        float v = outS[nl2 * 36 + jg];
        if (jg < 2)
            out[2 * n + jg] = pos[2 * n + jg] + v;
        else
            out[(size_t)NN * 2 + (size_t)n * CV + (jg - 2)]
                = g_x[(size_t)n * CV + (jg - 2)] + v;
    }
}

// ---------------- launch ----------------
extern "C" void kernel_launch(void* const* d_in, const int* in_sizes, int n_in,
                              void* d_out, int out_size) {
    (void)in_sizes; (void)n_in; (void)out_size;
    const float* positions = (const float*)d_in[0];
    const float* weights   = (const float*)d_in[1];
    // d_in[2] = batch (int32, uniform NB) — unused
    const float* kpos      = (const float*)d_in[3];
    const float* KW        = (const float*)d_in[4];
    const float* g1        = (const float*)d_in[5];
    const float* be1       = (const float*)d_in[6];
    const float* W1        = (const float*)d_in[7];
    const float* b1        = (const float*)d_in[8];
    const float* g2        = (const float*)d_in[9];
    const float* be2       = (const float*)d_in[10];
    const float* W2        = (const float*)d_in[11];
    const float* b2        = (const float*)d_in[12];
    float* out = (float*)d_out;

    k1_cw<<<128, 288>>>(weights, KW);
    k2_sample<<<512, 128>>>(positions, kpos);
    k3_xl<<<64, 256>>>();
    k4_mlp1<<<128, 256>>>(weights, g1, be1, W1, b1);
    k5_stats2<<<64, 256>>>();
    k6_final<<<128, 256>>>(positions, g2, be2, W2, b2, out);
}

// round 10
// speedup vs baseline: 1.7456x; 1.0186x over previous
#include <cuda_runtime.h>
#include <cstdint>

// Problem constants
#define NN   8192     // total points
#define NBV  1024     // points per batch
#define BV   8        // batches
#define KV   9        // kernel taps
#define CV   32       // channels
#define CMV  128      // hidden
#define CWROW 288     // K*C floats per point

// ---------------- static scratch (no allocs allowed) ----------------
__device__ __align__(16) float g_cw[NN * CWROW];        // conv_w, [n][k][c]
__device__ __align__(16) float g_part[8 * NN * CV];     // sampled partials (8 nb eighths)
__device__ __align__(16) float g_xl[NN * CV];           // leaky(sampled)
__device__ __align__(16) float g_x[NN * CV];            // bn1(xl)+weights
__device__ __align__(16) float g_hl[NN * CMV];          // leaky(x@W1+b1)
__device__ float g_p1s[64 * CV],  g_p1q[64 * CV];       // bn1 per-block partials
__device__ float g_p2s[64 * CMV], g_p2q[64 * CMV];      // bn2 per-block partials

// ---------------- packed f32x2 helpers ----------------
__device__ __forceinline__ unsigned long long pack2(float a, float b) {
    unsigned long long r;
    asm("mov.b64 %0, {%1, %2};" : "=l"(r) : "f"(a), "f"(b));
    return r;
}
__device__ __forceinline__ void unpack2(unsigned long long v, float& a, float& b) {
    asm("mov.b64 {%0, %1}, %2;" : "=f"(a), "=f"(b) : "l"(v));
}
__device__ __forceinline__ void fma2(unsigned long long& d, unsigned long long a,
                                     unsigned long long b) {
    asm("fma.rn.f32x2 %0, %1, %2, %3;" : "=l"(d) : "l"(a), "l"(b), "l"(d));
}
__device__ __forceinline__ unsigned long long mul2(unsigned long long a,
                                                   unsigned long long b) {
    unsigned long long r;
    asm("mul.rn.f32x2 %0, %1, %2;" : "=l"(r) : "l"(a), "l"(b));
    return r;
}

// ---------------- cp.async helpers ----------------
__device__ __forceinline__ uint32_t smem_u32(const void* p) {
    uint32_t a;
    asm("{ .reg .u64 t; cvta.to.shared.u64 t, %1; cvt.u32.u64 %0, t; }" : "=r"(a) : "l"(p));
    return a;
}
__device__ __forceinline__ void cpa16(uint32_t s, const void* g) {
    asm volatile("cp.async.cg.shared.global [%0], [%1], 16;" :: "r"(s), "l"(g));
}
#define CPA_COMMIT() asm volatile("cp.async.commit_group;" ::: "memory")
#define CPA_WAIT(n)  asm volatile("cp.async.wait_group %0;" :: "n"(n) : "memory")

// ---------------- K1: conv_w[n][k][d] = sum_c weights[n][c] * KW[k][c][d] ----------------
// 288 threads = (k = t/32, d = t%32); 128 blocks x 64 rows. KW cached in registers.
__global__ __launch_bounds__(288) void k1_cw(const float* __restrict__ weights,
                                             const float* __restrict__ KW) {
    __shared__ __align__(16) float wS[64 * CV];   // 8KB
    int t = threadIdx.x;
    int k = t / 32, d = t % 32;
    int n0 = blockIdx.x * 64;

    float KWr[CV];
#pragma unroll
    for (int c = 0; c < CV; c++) KWr[c] = KW[k * CV * CV + c * CV + d];  // coalesced per warp

    for (int i = t; i < 64 * CV; i += 288) wS[i] = weights[(size_t)n0 * CV + i];
    __syncthreads();

#pragma unroll 2
    for (int nl = 0; nl < 64; nl++) {
        const float4* wr = reinterpret_cast<const float4*>(&wS[nl * CV]);
        float acc = 0.f;
#pragma unroll
        for (int p = 0; p < 8; p++) {
            float4 v = wr[p];   // broadcast LDS.128
            acc += KWr[4*p+0] * v.x + KWr[4*p+1] * v.y
                 + KWr[4*p+2] * v.z + KWr[4*p+3] * v.w;
        }
        g_cw[(size_t)(n0 + nl) * CWROW + t] = acc;   // fully coalesced (288 consecutive)
    }
}

// ---------------- K2: fused Kmat * conv_w, FFMA2, cp.async double-buffered ----------------
// grid = 8 batches x 8 n-tiles(128) x 8 nb-eighths(128) = 512 CTAs, 128 threads.
#define NBT 16
__global__ __launch_bounds__(128) void k2_sample(const float* __restrict__ pos,
                                                 const float* __restrict__ kpos) {
    __shared__ __align__(16) float cwS[2][NBT * CWROW];   // 2 x 18KB
    __shared__ __align__(16) float pS[2][NBT * 2];

    int t    = threadIdx.x;
    int bid  = blockIdx.x;
    int q    = bid & 7;          // nb eighth
    int tile = (bid >> 3) & 7;   // n tile
    int b    = bid >> 6;         // batch

    int n = b * NBV + tile * 128 + t;
    float px = pos[2 * n], py = pos[2 * n + 1];

    // kernel grid is separable: kpos[k] = (g[k/3], g[k%3])
    float gvx[3], gvy[3];
#pragma unroll
    for (int i = 0; i < 3; i++) { gvx[i] = kpos[2 * (3 * i)]; gvy[i] = kpos[2 * i + 1]; }

    unsigned long long acc2[16];
#pragma unroll
    for (int i = 0; i < 16; i++) acc2[i] = 0ULL;

    int nb0 = b * NBV + q * 128;

    // stage chunk ci into buffer buf (cp.async, no completion here)
    auto stage = [&](int ci, int buf) {
        const float4* src = reinterpret_cast<const float4*>(
            &g_cw[(size_t)(nb0 + ci * NBT) * CWROW]);
        uint32_t dst = smem_u32(&cwS[buf][0]);
#pragma unroll
        for (int r = 0; r < 9; r++) {
            int i = t + 128 * r;
            cpa16(dst + 16 * i, src + i);
        }
        if (t < 8)
            cpa16(smem_u32(&pS[buf][0]) + 16 * t,
                  reinterpret_cast<const float4*>(&pos[(size_t)2 * (nb0 + ci * NBT)]) + t);
    };

    stage(0, 0);
    CPA_COMMIT();

#pragma unroll 1
    for (int ci = 0; ci < 8; ci++) {
        int buf = ci & 1;
        if (ci + 1 < 8) { stage(ci + 1, (ci + 1) & 1); CPA_COMMIT(); CPA_WAIT(1); }
        else           { CPA_WAIT(0); }
        __syncthreads();

#pragma unroll 1
        for (int j = 0; j < NBT; j++) {
            float dX = px - pS[buf][2 * j], dY = py - pS[buf][2 * j + 1];
            float ex[3], ey[3];
#pragma unroll
            for (int g = 0; g < 3; g++) {
                float ax = dX - gvx[g];
                float ay = dY - gvy[g];
                ex[g] = __expf(-2.0f * ax * ax);
                ey[g] = __expf(-2.0f * ay * ay);
            }
            unsigned long long ex2[3], ey2[3];
#pragma unroll
            for (int g = 0; g < 3; g++) {
                ex2[g] = pack2(ex[g], ex[g]);
                ey2[g] = pack2(ey[g], ey[g]);
            }
#pragma unroll
            for (int k = 0; k < KV; k++) {
                unsigned long long w2 = mul2(ex2[k / 3], ey2[k % 3]);
                const ulonglong2* cw2 =
                    reinterpret_cast<const ulonglong2*>(&cwS[buf][j * CWROW + k * CV]);
#pragma unroll
                for (int p = 0; p < 8; p++) {
                    ulonglong2 v = cw2[p];
                    fma2(acc2[2 * p],     v.x, w2);
                    fma2(acc2[2 * p + 1], v.y, w2);
                }
            }
        }
        __syncthreads();   // all warps done with buf before it is restaged
    }

    float* outp = &g_part[(size_t)q * NN * CV + (size_t)n * CV];
#pragma unroll
    for (int p = 0; p < 8; p++) {
        float4 v;
        unpack2(acc2[2 * p],     v.x, v.y);
        unpack2(acc2[2 * p + 1], v.z, v.w);
        reinterpret_cast<float4*>(outp)[p] = v;
    }
}

// ---------------- K3: xl = leaky(sum of 8 partials); coalesced per-block stats ----------------
__global__ __launch_bounds__(256) void k3_xl(void) {
    int t = threadIdx.x, blk = blockIdx.x;
    size_t base = (size_t)blk * 128 * CV;
    float s = 0.f, s2 = 0.f;
    for (int idx = t; idx < 128 * CV; idx += 256) {
        size_t off = base + idx;
        float v = 0.f;
#pragma unroll
        for (int sl = 0; sl < 8; sl++) v += g_part[(size_t)sl * NN * CV + off];
        float xl = (v >= 0.f) ? v : 0.01f * v;
        g_xl[off] = xl;
        s += xl; s2 += xl * xl;
    }
    __shared__ float rs[256], rq[256];
    rs[t] = s; rq[t] = s2; __syncthreads();
    if (t < CV) {
        float a = 0.f, bb = 0.f;
#pragma unroll
        for (int j = 0; j < 256; j += 32) { a += rs[t + j]; bb += rq[t + j]; }
        g_p1s[blk * CV + t] = a; g_p1q[blk * CV + t] = bb;
    }
}

// ---------------- K4: x = bn1(xl)+weights; hl = leaky(x@W1+b1), FFMA2 ----------------
// grid = 256 blocks x 256 threads; block = 32 n-rows x 8 j-groups(16 each).
__global__ __launch_bounds__(256) void k4_mlp1(const float* __restrict__ weights,
                                               const float* __restrict__ gamma1,
                                               const float* __restrict__ beta1,
                                               const float* __restrict__ W1,
                                               const float* __restrict__ b1) {
    __shared__ __align__(16) float W1s[CV * CMV];
    __shared__ float xS[32 * 33];
    __shared__ float sc1[CV], sh1[CV], b1s[CMV];
    __shared__ float rs[256], rq[256];
    int t = threadIdx.x, blk = blockIdx.x;
    int n0 = blk * 32;

    for (int i = t; i < CV * CMV; i += 256) W1s[i] = W1[i];
    if (t < CMV) b1s[t] = b1[t];
    for (int i = t; i < 32 * CV; i += 256) {
        int nl = i >> 5, c = i & 31;
        xS[nl * 33 + c] = g_xl[(size_t)(n0 + nl) * CV + c];
    }
    {
        int c = t & 31, g = t >> 5;
        float s = 0.f, s2 = 0.f;
        for (int j = g; j < 64; j += 8) { s += g_p1s[j * CV + c]; s2 += g_p1q[j * CV + c]; }
        rs[t] = s; rq[t] = s2;
    }
    __syncthreads();
    if (t < CV) {
        float s = 0.f, s2 = 0.f;
#pragma unroll
        for (int g = 0; g < 8; g++) { s += rs[g * 32 + t]; s2 += rq[g * 32 + t]; }
        float mu  = s * (1.0f / NN);
        float var = s2 * (1.0f / NN) - mu * mu;
        float inv = rsqrtf(var + 1e-5f);
        float sc  = gamma1[t] * inv;
        sc1[t] = sc; sh1[t] = beta1[t] - mu * sc;
    }
    __syncthreads();

    for (int i = t; i < 32 * CV; i += 256) {
        int nl = i >> 5, c = i & 31;
        float xv = fmaf(xS[nl * 33 + c], sc1[c], sh1[c])
                 + weights[(size_t)(n0 + nl) * CV + c];
        xS[nl * 33 + c] = xv;
        g_x[(size_t)(n0 + nl) * CV + c] = xv;
    }
    __syncthreads();

    int nl = t & 31, jq = t >> 5, jb = jq * 16;
    unsigned long long acc2[8];
#pragma unroll
    for (int i = 0; i < 8; i++) acc2[i] = pack2(b1s[jb + 2 * i], b1s[jb + 2 * i + 1]);
#pragma unroll
    for (int c = 0; c < CV; c++) {
        float xc = xS[nl * 33 + c];
        unsigned long long xc2 = pack2(xc, xc);
        const ulonglong2* wr = reinterpret_cast<const ulonglong2*>(&W1s[c * CMV + jb]);
#pragma unroll
        for (int p = 0; p < 4; p++) {
            ulonglong2 v = wr[p];   // broadcast LDS.128
            fma2(acc2[2 * p],     v.x, xc2);
            fma2(acc2[2 * p + 1], v.y, xc2);
        }
    }
    float* hl = &g_hl[(size_t)(n0 + nl) * CMV + jb];
#pragma unroll
    for (int p = 0; p < 4; p++) {
        float h0, h1, h2, h3;
        unpack2(acc2[2 * p],     h0, h1);
        unpack2(acc2[2 * p + 1], h2, h3);
        float4 v;
        v.x = (h0 >= 0.f) ? h0 : 0.01f * h0;
        v.y = (h1 >= 0.f) ? h1 : 0.01f * h1;
        v.z = (h2 >= 0.f) ? h2 : 0.01f * h2;
        v.w = (h3 >= 0.f) ? h3 : 0.01f * h3;
        reinterpret_cast<float4*>(hl)[p] = v;
    }
}

// ---------------- K5: bn2 partial sums, coalesced ----------------
__global__ __launch_bounds__(256) void k5_stats2(void) {
    int t = threadIdx.x, blk = blockIdx.x;
    size_t base = (size_t)blk * 128 * CMV;
    float s = 0.f, s2 = 0.f;
    for (int idx = t; idx < 128 * CMV; idx += 256) {
        float v = g_hl[base + idx];
        s += v; s2 += v * v;
    }
    __shared__ float rs[256], rq[256];
    rs[t] = s; rq[t] = s2; __syncthreads();
    if (t < CMV) {
        g_p2s[blk * CMV + t] = rs[t] + rs[t + CMV];
        g_p2q[blk * CMV + t] = rq[t] + rq[t + CMV];
    }
}

// ---------------- K6: h = bn2(hl); mlp_out = h@W2 + b2; outputs via SMEM bounce ----------------
// grid = 128 blocks x 256 threads; block = 64 n-rows x 4 j-groups(9 each).
__global__ __launch_bounds__(256) void k6_final(const float* __restrict__ pos,
                                                const float* __restrict__ gamma2,
                                                const float* __restrict__ beta2,
                                                const float* __restrict__ W2,
                                                const float* __restrict__ b2,
                                                float* __restrict__ out) {
    __shared__ float W2s[CMV * 36];     // 18KB (padded 34->36)
    __shared__ float hlS[64 * 129];     // 33KB normalized h tile, pad 129
    __shared__ float outS[64 * 36];     // 9.2KB output bounce
    __shared__ float sc2[CMV], sh2[CMV], b2s[36];
    __shared__ float rs[256], rq[256];
    int t = threadIdx.x, blk = blockIdx.x;
    int n0 = blk * 64;

    for (int i = t; i < CMV * 36; i += 256) {
        int d = i / 36, j = i % 36;
        W2s[i] = (j < 34) ? W2[d * 34 + j] : 0.f;
    }
    if (t < 36) b2s[t] = (t < 34) ? b2[t] : 0.f;
    {
        int c = t & 127, hf = t >> 7;
        float s = 0.f, s2 = 0.f;
#pragma unroll 8
        for (int j = hf * 32; j < hf * 32 + 32; j++) {
            s += g_p2s[j * CMV + c]; s2 += g_p2q[j * CMV + c];
        }
        rs[t] = s; rq[t] = s2;
    }
    __syncthreads();
    if (t < CMV) {
        float s  = rs[t] + rs[t + 128];
        float s2 = rq[t] + rq[t + 128];
        float mu  = s * (1.0f / NN);
        float var = s2 * (1.0f / NN) - mu * mu;
        float inv = rsqrtf(var + 1e-5f);
        float sc  = gamma2[t] * inv;
        sc2[t] = sc; sh2[t] = beta2[t] - mu * sc;
    }
    __syncthreads();

    // stage normalized h tile, coalesced reads
    for (int i = t; i < 64 * CMV; i += 256) {
        int nl = i >> 7, d = i & 127;
        hlS[nl * 129 + d] = fmaf(g_hl[(size_t)n0 * CMV + i], sc2[d], sh2[d]);
    }
    __syncthreads();

    int nl = t & 63, qq = t >> 6, jb = qq * 9;
    float acc[9];
#pragma unroll
    for (int j = 0; j < 9; j++) acc[j] = b2s[jb + j];
#pragma unroll 4
    for (int d = 0; d < CMV; d++) {
        float hn = hlS[nl * 129 + d];
        const float* wr = &W2s[d * 36 + jb];
#pragma unroll
        for (int j = 0; j < 9; j++) acc[j] += hn * wr[j];
    }
#pragma unroll
    for (int j = 0; j < 9; j++) outS[nl * 36 + jb + j] = acc[j];
    __syncthreads();

    // coalesced output writes
    for (int i = t; i < 64 * 34; i += 256) {
        int nl2 = i / 34, jg = i % 34;
        int n = n0 + nl2;
        float v = outS[nl2 * 36 + jg];
        if (jg < 2)
            out[2 * n + jg] = pos[2 * n + jg] + v;
        else
            out[(size_t)NN * 2 + (size_t)n * CV + (jg - 2)]
                = g_x[(size_t)n * CV + (jg - 2)] + v;
    }
}

// ---------------- launch ----------------
extern "C" void kernel_launch(void* const* d_in, const int* in_sizes, int n_in,
                              void* d_out, int out_size) {
    (void)in_sizes; (void)n_in; (void)out_size;
    const float* positions = (const float*)d_in[0];
    const float* weights   = (const float*)d_in[1];
    // d_in[2] = batch (int32, uniform NB) — unused
    const float* kpos      = (const float*)d_in[3];
    const float* KW        = (const float*)d_in[4];
    const float* g1        = (const float*)d_in[5];
    const float* be1       = (const float*)d_in[6];
    const float* W1        = (const float*)d_in[7];
    const float* b1        = (const float*)d_in[8];
    const float* g2        = (const float*)d_in[9];
    const float* be2       = (const float*)d_in[10];
    const float* W2        = (const float*)d_in[11];
    const float* b2        = (const float*)d_in[12];
    float* out = (float*)d_out;

    k1_cw<<<128, 288>>>(weights, KW);
    k2_sample<<<512, 128>>>(positions, kpos);
    k3_xl<<<64, 256>>>();
    k4_mlp1<<<256, 256>>>(weights, g1, be1, W1, b1);
    k5_stats2<<<64, 256>>>();
    k6_final<<<128, 256>>>(positions, g2, be2, W2, b2, out);
}